// round 12
// baseline (speedup 1.0000x reference)
#include <cuda_runtime.h>

// JPEG compress/decompress (DiffJPEG, factor=1.0) for [16,3,512,512] fp32 in [-1,1].
// One CTA = one 64x32 tile, 256 threads, 6 CTAs/SM.
// Phase 1: gmem -> YCbCr -> lane-pair half row-DCT -> smem (permuted freq slots)
// Phase 2: packed f32x2 column pass, two sequential passes; thread owns columns
//          {c2, c2+1, c2+32, c2+33} so every LDS.64/STS.64 covers all 32 banks
//          (2 wavefronts, conflict-free): col DCT + diff-round quant + col IDCT.
// Phase 3: smem -> half row-IDCT (coeffs pre-scaled by 1/255) -> YCbCr->RGB
//          via __saturatef -> gmem.
// DC trick: subtract 128*64 from the DC coefficient; re-add (128/255) at output.

namespace {

constexpr int Hh = 512;
constexpr int Ww = 512;
constexpr int TW = 64;
constexpr int TH = 32;
constexpr int PL = TW * TH;   // 2048 floats per channel plane

typedef unsigned long long u64;

__device__ __forceinline__ u64 F2PK(float a, float b) {
  u64 r; asm("mov.b64 %0,{%1,%2};" : "=l"(r) : "f"(a), "f"(b)); return r;
}
__device__ __forceinline__ u64 FMA2(u64 a, u64 b, u64 c) {
  u64 d; asm("fma.rn.f32x2 %0,%1,%2,%3;" : "=l"(d) : "l"(a), "l"(b), "l"(c)); return d;
}
__device__ __forceinline__ u64 ADD2(u64 a, u64 b) {
  u64 d; asm("add.rn.f32x2 %0,%1,%2;" : "=l"(d) : "l"(a), "l"(b)); return d;
}
__device__ __forceinline__ u64 SUB2(u64 a, u64 b) {
  u64 d; asm("sub.rn.f32x2 %0,%1,%2;" : "=l"(d) : "l"(a), "l"(b)); return d;
}
__device__ __forceinline__ u64 MUL2(u64 a, u64 b) {
  u64 d; asm("mul.rn.f32x2 %0,%1,%2;" : "=l"(d) : "l"(a), "l"(b)); return d;
}

// Forward half-transform coefs: CF[p][m][k] = Dm[2m+p][k], k=0..3
__constant__ float CF[32] = {
  1.f,          1.f,          1.f,          1.f,
  0.92387953f,  0.38268343f, -0.38268343f, -0.92387953f,
  0.70710678f, -0.70710678f, -0.70710678f,  0.70710678f,
  0.38268343f, -0.92387953f,  0.92387953f, -0.38268343f,
  0.98078528f,  0.83146961f,  0.55557023f,  0.19509032f,
  0.83146961f, -0.19509032f, -0.98078528f, -0.55557023f,
  0.55557023f, -0.98078528f,  0.19509032f,  0.83146961f,
  0.19509032f, -0.55557023f,  0.83146961f, -0.98078528f,
};
// Inverse half-transform coefs: CI[p][k][m] = Dm[2m+p][k]
__constant__ float CI[32] = {
  1.f,  0.92387953f,  0.70710678f,  0.38268343f,
  1.f,  0.38268343f, -0.70710678f, -0.92387953f,
  1.f, -0.38268343f, -0.70710678f,  0.92387953f,
  1.f, -0.92387953f,  0.70710678f, -0.38268343f,
  0.98078528f,  0.83146961f,  0.55557023f,  0.19509032f,
  0.83146961f, -0.19509032f, -0.98078528f, -0.55557023f,
  0.55557023f, -0.98078528f,  0.19509032f,  0.83146961f,
  0.19509032f, -0.55557023f,  0.83146961f, -0.98078528f,
};

__device__ static const float QY[64] = {
  16, 11, 10, 16, 24, 40, 51, 61,
  12, 12, 14, 19, 26, 58, 60, 55,
  14, 13, 16, 24, 40, 57, 69, 56,
  14, 17, 22, 29, 51, 87, 80, 62,
  18, 22, 37, 56, 68, 109, 103, 77,
  24, 35, 55, 64, 81, 104, 113, 92,
  49, 64, 78, 87, 103, 121, 120, 101,
  72, 92, 95, 98, 112, 100, 103, 99
};
__device__ static const float QC[64] = {
  17, 18, 24, 47, 99, 99, 99, 99,
  18, 21, 26, 66, 99, 99, 99, 99,
  24, 26, 56, 99, 99, 99, 99, 99,
  47, 66, 99, 99, 99, 99, 99, 99,
  99, 99, 99, 99, 99, 99, 99, 99,
  99, 99, 99, 99, 99, 99, 99, 99,
  99, 99, 99, 99, 99, 99, 99, 99,
  99, 99, 99, 99, 99, 99, 99, 99
};

__device__ __forceinline__ int swzc(int c) { return c ^ ((c & 32) >> 3); }

// Packed coefficient indices (positive only; signs via SUB2)
enum { K_C4 = 0, K_C2, K_C6, K_C1, K_C3, K_C5, K_C7, K_NUM };

// Packed 8-point DCT-II (two independent columns per u64)
__device__ __forceinline__ void dct2(u64* v, const u64* C) {
  u64 e0 = ADD2(v[0], v[7]), e1 = ADD2(v[1], v[6]);
  u64 e2 = ADD2(v[2], v[5]), e3 = ADD2(v[3], v[4]);
  u64 o0 = SUB2(v[0], v[7]), o1 = SUB2(v[1], v[6]);
  u64 o2 = SUB2(v[2], v[5]), o3 = SUB2(v[3], v[4]);
  u64 s03 = ADD2(e0, e3), s12 = ADD2(e1, e2);
  u64 d03 = SUB2(e0, e3), d12 = SUB2(e1, e2);
  v[0] = ADD2(s03, s12);
  v[4] = MUL2(C[K_C4], SUB2(s03, s12));
  v[2] = FMA2(C[K_C6], d12, MUL2(C[K_C2], d03));
  v[6] = SUB2(MUL2(C[K_C6], d03), MUL2(C[K_C2], d12));
  v[1] = FMA2(C[K_C7], o3, FMA2(C[K_C5], o2, FMA2(C[K_C3], o1, MUL2(C[K_C1], o0))));
  v[3] = SUB2(MUL2(C[K_C3], o0),
              FMA2(C[K_C7], o1, FMA2(C[K_C1], o2, MUL2(C[K_C5], o3))));
  v[5] = SUB2(FMA2(C[K_C7], o2, FMA2(C[K_C3], o3, MUL2(C[K_C5], o0))),
              MUL2(C[K_C1], o1));
  v[7] = SUB2(FMA2(C[K_C3], o2, MUL2(C[K_C7], o0)),
              FMA2(C[K_C1], o3, MUL2(C[K_C5], o1)));
}

// Packed 8-point IDCT (alpha folded into tables)
__device__ __forceinline__ void idct2(u64* v, const u64* C) {
  u64 t = MUL2(C[K_C4], v[4]);
  u64 p = ADD2(v[0], t);
  u64 m = SUB2(v[0], t);
  u64 u1 = FMA2(C[K_C6], v[6], MUL2(C[K_C2], v[2]));
  u64 u2 = SUB2(MUL2(C[K_C6], v[2]), MUL2(C[K_C2], v[6]));
  u64 ev0 = ADD2(p, u1), ev3 = SUB2(p, u1);
  u64 ev1 = ADD2(m, u2), ev2 = SUB2(m, u2);
  u64 i1 = v[1], i3 = v[3], i5 = v[5], i7 = v[7];
  u64 od0 = FMA2(C[K_C7], i7, FMA2(C[K_C5], i5, FMA2(C[K_C3], i3, MUL2(C[K_C1], i1))));
  u64 od1 = SUB2(MUL2(C[K_C3], i1),
                 FMA2(C[K_C7], i3, FMA2(C[K_C1], i5, MUL2(C[K_C5], i7))));
  u64 od2 = SUB2(FMA2(C[K_C7], i5, FMA2(C[K_C3], i7, MUL2(C[K_C5], i1))),
                 MUL2(C[K_C1], i3));
  u64 od3 = SUB2(FMA2(C[K_C3], i5, MUL2(C[K_C7], i1)),
                 FMA2(C[K_C1], i7, MUL2(C[K_C5], i3)));
  v[0] = ADD2(ev0, od0);  v[7] = SUB2(ev0, od0);
  v[1] = ADD2(ev1, od1);  v[6] = SUB2(ev1, od1);
  v[2] = ADD2(ev2, od2);  v[5] = SUB2(ev2, od2);
  v[3] = ADD2(ev3, od3);  v[4] = SUB2(ev3, od3);
}

// Lane-pair half row-DCT (even lane: natural px, odd lane: reversed px)
__device__ __forceinline__ void half_dct(float v[4], const float cf[16], float sgn) {
  float t0 = __shfl_xor_sync(0xffffffffu, v[0], 1);
  float t1 = __shfl_xor_sync(0xffffffffu, v[1], 1);
  float t2 = __shfl_xor_sync(0xffffffffu, v[2], 1);
  float t3 = __shfl_xor_sync(0xffffffffu, v[3], 1);
  float x0 = fmaf(sgn, v[0], t0);
  float x1 = fmaf(sgn, v[1], t1);
  float x2 = fmaf(sgn, v[2], t2);
  float x3 = fmaf(sgn, v[3], t3);
  v[0] = fmaf(cf[3],  x3, fmaf(cf[2],  x2, fmaf(cf[1],  x1, cf[0]  * x0)));
  v[1] = fmaf(cf[7],  x3, fmaf(cf[6],  x2, fmaf(cf[5],  x1, cf[4]  * x0)));
  v[2] = fmaf(cf[11], x3, fmaf(cf[10], x2, fmaf(cf[9],  x1, cf[8]  * x0)));
  v[3] = fmaf(cf[15], x3, fmaf(cf[14], x2, fmaf(cf[13], x1, cf[12] * x0)));
}

// Lane-pair half row-IDCT (even lane out: natural px, odd lane out: reversed px)
__device__ __forceinline__ void half_idct(float f[4], const float ci[16], float sgn) {
  float g0 = fmaf(ci[3],  f[3], fmaf(ci[2],  f[2], fmaf(ci[1],  f[1], ci[0]  * f[0])));
  float g1 = fmaf(ci[7],  f[3], fmaf(ci[6],  f[2], fmaf(ci[5],  f[1], ci[4]  * f[0])));
  float g2 = fmaf(ci[11], f[3], fmaf(ci[10], f[2], fmaf(ci[9],  f[1], ci[8]  * f[0])));
  float g3 = fmaf(ci[15], f[3], fmaf(ci[14], f[2], fmaf(ci[13], f[1], ci[12] * f[0])));
  float t0 = __shfl_xor_sync(0xffffffffu, g0, 1);
  float t1 = __shfl_xor_sync(0xffffffffu, g1, 1);
  float t2 = __shfl_xor_sync(0xffffffffu, g2, 1);
  float t3 = __shfl_xor_sync(0xffffffffu, g3, 1);
  f[0] = fmaf(sgn, g0, t0);
  f[1] = fmaf(sgn, g1, t1);
  f[2] = fmaf(sgn, g2, t2);
  f[3] = fmaf(sgn, g3, t3);
}

__global__ void __launch_bounds__(256, 6)
jpeg_kernel(const float* __restrict__ in, float* __restrict__ out) {
  extern __shared__ float sm[];         // 3*2048 planes + 128 SA + 128 SB
  float* sQA = sm + 3 * PL;             // slot-permuted: 0.25*au*av / Q
  float* sQB = sm + 3 * PL + 128;       // slot-permuted: 0.25*au*av * Q

  const int tid = threadIdx.x;
  const bool oddl = (tid & 1) != 0;
  const float sgn = oddl ? -1.f : 1.f;
  const int gx0 = blockIdx.x * TW;
  const int gy0 = blockIdx.y * TH;
  const size_t plane = (size_t)Hh * Ww;
  const size_t img = (size_t)blockIdx.z * 3 * plane;
  const float* __restrict__ pr = in + img;
  const float* __restrict__ pg = in + img + plane;
  const float* __restrict__ pb = in + img + 2 * plane;

  // ---- quant table fill (slot s holds freq perm[s] = {0,2,4,6,1,3,5,7}) ----
  if (tid < 128) {
    int tab = tid >> 6, uv = tid & 63, u = uv >> 3, s = uv & 7;
    int v = (s < 4) ? (s << 1) : ((s << 1) - 7);
    float a = 0.25f * (u ? 1.f : 0.70710678118654752f)
                    * (v ? 1.f : 0.70710678118654752f);
    float Q = tab ? QC[u * 8 + v] : QY[u * 8 + v];
    sQA[tid] = a / Q;
    sQB[tid] = a * Q;
  }

  // ------- Phase 1: gmem -> YCbCr -> half row-DCT -> smem (channel-serial) -------
  {
    float cf[16];
    const float* cfp = CF + (oddl ? 16 : 0);
#pragma unroll
    for (int t = 0; t < 16; ++t) cf[t] = cfp[t];

#pragma unroll
    for (int it = 0; it < 2; ++it) {
      int i = tid + it * 256;
      int row = i >> 4;                 // 0..31
      int c4 = (i & 15) << 2;
      size_t g = (size_t)(gy0 + row) * Ww + (gx0 + c4);
      float4 r4 = *(const float4*)(pr + g);
      float4 g4 = *(const float4*)(pg + g);
      float4 b4 = *(const float4*)(pb + g);

      // odd lanes reverse their 4 pixels (pixel order 8j+7..8j+4)
      float R[4], G[4], B[4];
      R[0] = oddl ? r4.w : r4.x;  R[1] = oddl ? r4.z : r4.y;
      R[2] = oddl ? r4.y : r4.z;  R[3] = oddl ? r4.x : r4.w;
      G[0] = oddl ? g4.w : g4.x;  G[1] = oddl ? g4.z : g4.y;
      G[2] = oddl ? g4.y : g4.z;  G[3] = oddl ? g4.x : g4.w;
      B[0] = oddl ? b4.w : b4.x;  B[1] = oddl ? b4.z : b4.y;
      B[2] = oddl ? b4.y : b4.z;  B[3] = oddl ? b4.x : b4.w;

      int s = row * 64 + swzc(c4);

      float ch[4];
#pragma unroll
      for (int q = 0; q < 4; ++q)   // Y ((x+1)/2*255 folded in)
        ch[q] = fmaf(38.1225f, R[q], fmaf(74.8425f, G[q], fmaf(14.535f, B[q], 127.5f)));
      half_dct(ch, cf, sgn);
      *(float4*)&sm[s] = make_float4(ch[0], ch[1], ch[2], ch[3]);

#pragma unroll
      for (int q = 0; q < 4; ++q)   // Cb
        ch[q] = fmaf(-21.51384f, R[q], fmaf(-42.23616f, G[q], fmaf(63.75f, B[q], 128.f)));
      half_dct(ch, cf, sgn);
      *(float4*)&sm[PL + s] = make_float4(ch[0], ch[1], ch[2], ch[3]);

#pragma unroll
      for (int q = 0; q < 4; ++q)   // Cr
        ch[q] = fmaf(63.75f, R[q], fmaf(-53.38272f, G[q], fmaf(-10.36728f, B[q], 128.f)));
      half_dct(ch, cf, sgn);
      *(float4*)&sm[2 * PL + s] = make_float4(ch[0], ch[1], ch[2], ch[3]);
    }
  }
  __syncthreads();

  // --- Phase 2: packed f32x2 column pass, two sequential passes.
  // Thread owns column pairs (c2, c2+1) and (c2+32, c2+33): each pass's 16
  // lanes per block-row group span all 32 banks -> LDS.64/STS.64 = 2 wf.
  if (tid < 192) {
    const int k = tid >> 6;
    const int idx = tid & 63;
    const int c2 = (idx & 15) << 1;     // even column in [0,30]
    const int br = idx >> 4;            // 0..3
    const int slot = c2 & 7;            // 0,2,4,6 (lo element's freq slot)
    const int koff = k ? 64 : 0;
    const int base = k * PL + br * 512;

    u64 C[K_NUM];
    C[K_C4] = F2PK(0.70710678f, 0.70710678f);
    C[K_C2] = F2PK(0.92387953f, 0.92387953f);
    C[K_C6] = F2PK(0.38268343f, 0.38268343f);
    C[K_C1] = F2PK(0.98078528f, 0.98078528f);
    C[K_C3] = F2PK(0.83146961f, 0.83146961f);
    C[K_C5] = F2PK(0.55557023f, 0.55557023f);
    C[K_C7] = F2PK(0.19509032f, 0.19509032f);
    const u64 MAG = F2PK(12582912.f, 12582912.f);   // 1.5*2^23 (RNE magic)

#pragma unroll
    for (int pass = 0; pass < 2; ++pass) {
      const int adr = base + swzc(c2 + pass * 32);
      u64 v[8];
#pragma unroll
      for (int r = 0; r < 8; ++r)
        v[r] = *(const u64*)&sm[adr + r * 64];
      dct2(v, C);
      if (slot == 0)                                 // DC column (lo element)
        v[0] = ADD2(v[0], F2PK(-8192.f, 0.f));
#pragma unroll
      for (int u = 0; u < 8; ++u) {
        u64 qa = *(const u64*)&sQA[koff + u * 8 + slot];
        u64 qb = *(const u64*)&sQB[koff + u * 8 + slot];
        u64 s = MUL2(v[u], qa);
        u64 r = SUB2(ADD2(s, MAG), MAG);             // RNE round
        u64 d = SUB2(s, r);
        v[u] = MUL2(FMA2(MUL2(d, d), d, r), qb);     // diff_round + dequant
      }
      idct2(v, C);
#pragma unroll
      for (int r = 0; r < 8; ++r)
        *(u64*)&sm[adr + r * 64] = v[r];
    }
  }
  __syncthreads();

  // ------- Phase 3: smem -> half row-IDCT (x 1/255) -> RGB -> gmem -------
  {
    float ci[16];
    const float* cip = CI + (oddl ? 16 : 0);
    const float inv255 = 1.0f / 255.0f;
#pragma unroll
    for (int t = 0; t < 16; ++t) ci[t] = cip[t] * inv255;   // fold 1/255

    float* __restrict__ qr = out + img;
    float* __restrict__ qg = out + img + plane;
    float* __restrict__ qb2 = out + img + 2 * plane;

#pragma unroll
    for (int it = 0; it < 2; ++it) {
      int i = tid + it * 256;
      int row = i >> 4;
      int c4 = (i & 15) << 2;
      int s = row * 64 + swzc(c4);

      float y[4], cb[4], cr[4];
      float4 t4;
      t4 = *(const float4*)&sm[s];
      y[0]=t4.x; y[1]=t4.y; y[2]=t4.z; y[3]=t4.w;
      half_idct(y, ci, sgn);
      t4 = *(const float4*)&sm[PL + s];
      cb[0]=t4.x; cb[1]=t4.y; cb[2]=t4.z; cb[3]=t4.w;
      half_idct(cb, ci, sgn);
      t4 = *(const float4*)&sm[2 * PL + s];
      cr[0]=t4.x; cr[1]=t4.y; cr[2]=t4.z; cr[3]=t4.w;
      half_idct(cr, ci, sgn);

      float R[4], G[4], B[4];
#pragma unroll
      for (int q = 0; q < 4; ++q) {
        float y128 = y[q] + 0.501960784f;    // += 128/255 (DC trick, scaled)
        R[q] = __saturatef(fmaf(1.402f, cr[q], y128));
        G[q] = __saturatef(fmaf(-0.714136f, cr[q], fmaf(-0.344136f, cb[q], y128)));
        B[q] = __saturatef(fmaf(1.772f, cb[q], y128));
      }
      size_t g = (size_t)(gy0 + row) * Ww + (gx0 + c4);
      float4 ro = oddl ? make_float4(R[3], R[2], R[1], R[0]) : make_float4(R[0], R[1], R[2], R[3]);
      float4 go = oddl ? make_float4(G[3], G[2], G[1], G[0]) : make_float4(G[0], G[1], G[2], G[3]);
      float4 bo = oddl ? make_float4(B[3], B[2], B[1], B[0]) : make_float4(B[0], B[1], B[2], B[3]);
      *(float4*)(qr + g)  = ro;
      *(float4*)(qg + g)  = go;
      *(float4*)(qb2 + g) = bo;
    }
  }
}

} // namespace

extern "C" void kernel_launch(void* const* d_in, const int* in_sizes, int n_in,
                              void* d_out, int out_size) {
  (void)in_sizes; (void)n_in; (void)out_size;
  const float* in = (const float*)d_in[0];
  float* out = (float*)d_out;
  constexpr int SMEM = (3 * PL + 256) * 4;   // 25600 bytes
  static bool attr_set = false;
  if (!attr_set) {
    cudaFuncSetAttribute(jpeg_kernel, cudaFuncAttributeMaxDynamicSharedMemorySize, SMEM);
    attr_set = true;
  }
  dim3 grid(Ww / TW, Hh / TH, 16);
  jpeg_kernel<<<grid, 256, SMEM>>>(in, out);
}

// round 13
// speedup vs baseline: 1.0918x; 1.0918x over previous
#include <cuda_runtime.h>

// JPEG compress/decompress (DiffJPEG, factor=1.0) for [16,3,512,512] fp32 in [-1,1].
// One CTA = one 64x32 tile, 256 threads, 5 CTAs/SM.
// Phase 1: gmem -> YCbCr -> lane-pair half row-DCT -> smem (permuted freq slots)
// Phase 2: packed f32x2 column pass, ALL 256 threads (384 work items: channels
//          0,1 -> tid 0..255; channel 2 -> tid 0..127). Conflict-free u64
//          accesses; fused ulonglong2 quant table (1 LDS.128 per u).
// Phase 3: smem -> half row-IDCT (coeffs pre-scaled by 1/255) -> YCbCr->RGB
//          via __saturatef -> gmem.
// DC trick: subtract 128*64 from the DC coefficient; re-add (128/255) at output.

namespace {

constexpr int Hh = 512;
constexpr int Ww = 512;
constexpr int TW = 64;
constexpr int TH = 32;
constexpr int PL = TW * TH;   // 2048 floats per channel plane

typedef unsigned long long u64;

__device__ __forceinline__ u64 F2PK(float a, float b) {
  u64 r; asm("mov.b64 %0,{%1,%2};" : "=l"(r) : "f"(a), "f"(b)); return r;
}
__device__ __forceinline__ u64 FMA2(u64 a, u64 b, u64 c) {
  u64 d; asm("fma.rn.f32x2 %0,%1,%2,%3;" : "=l"(d) : "l"(a), "l"(b), "l"(c)); return d;
}
__device__ __forceinline__ u64 ADD2(u64 a, u64 b) {
  u64 d; asm("add.rn.f32x2 %0,%1,%2;" : "=l"(d) : "l"(a), "l"(b)); return d;
}
__device__ __forceinline__ u64 SUB2(u64 a, u64 b) {
  u64 d; asm("sub.rn.f32x2 %0,%1,%2;" : "=l"(d) : "l"(a), "l"(b)); return d;
}
__device__ __forceinline__ u64 MUL2(u64 a, u64 b) {
  u64 d; asm("mul.rn.f32x2 %0,%1,%2;" : "=l"(d) : "l"(a), "l"(b)); return d;
}

// Forward half-transform coefs: CF[p][m][k] = Dm[2m+p][k], k=0..3
__constant__ float CF[32] = {
  1.f,          1.f,          1.f,          1.f,
  0.92387953f,  0.38268343f, -0.38268343f, -0.92387953f,
  0.70710678f, -0.70710678f, -0.70710678f,  0.70710678f,
  0.38268343f, -0.92387953f,  0.92387953f, -0.38268343f,
  0.98078528f,  0.83146961f,  0.55557023f,  0.19509032f,
  0.83146961f, -0.19509032f, -0.98078528f, -0.55557023f,
  0.55557023f, -0.98078528f,  0.19509032f,  0.83146961f,
  0.19509032f, -0.55557023f,  0.83146961f, -0.98078528f,
};
// Inverse half-transform coefs: CI[p][k][m] = Dm[2m+p][k]
__constant__ float CI[32] = {
  1.f,  0.92387953f,  0.70710678f,  0.38268343f,
  1.f,  0.38268343f, -0.70710678f, -0.92387953f,
  1.f, -0.38268343f, -0.70710678f,  0.92387953f,
  1.f, -0.92387953f,  0.70710678f, -0.38268343f,
  0.98078528f,  0.83146961f,  0.55557023f,  0.19509032f,
  0.83146961f, -0.19509032f, -0.98078528f, -0.55557023f,
  0.55557023f, -0.98078528f,  0.19509032f,  0.83146961f,
  0.19509032f, -0.55557023f,  0.83146961f, -0.98078528f,
};

__device__ static const float QY[64] = {
  16, 11, 10, 16, 24, 40, 51, 61,
  12, 12, 14, 19, 26, 58, 60, 55,
  14, 13, 16, 24, 40, 57, 69, 56,
  14, 17, 22, 29, 51, 87, 80, 62,
  18, 22, 37, 56, 68, 109, 103, 77,
  24, 35, 55, 64, 81, 104, 113, 92,
  49, 64, 78, 87, 103, 121, 120, 101,
  72, 92, 95, 98, 112, 100, 103, 99
};
__device__ static const float QC[64] = {
  17, 18, 24, 47, 99, 99, 99, 99,
  18, 21, 26, 66, 99, 99, 99, 99,
  24, 26, 56, 99, 99, 99, 99, 99,
  47, 66, 99, 99, 99, 99, 99, 99,
  99, 99, 99, 99, 99, 99, 99, 99,
  99, 99, 99, 99, 99, 99, 99, 99,
  99, 99, 99, 99, 99, 99, 99, 99,
  99, 99, 99, 99, 99, 99, 99, 99
};

__device__ __forceinline__ int swzc(int c) { return c ^ ((c & 32) >> 3); }

// Packed coefficient indices (positive only; signs via SUB2)
enum { K_C4 = 0, K_C2, K_C6, K_C1, K_C3, K_C5, K_C7, K_NUM };

// Packed 8-point DCT-II (two independent columns per u64)
__device__ __forceinline__ void dct2(u64* v, const u64* C) {
  u64 e0 = ADD2(v[0], v[7]), e1 = ADD2(v[1], v[6]);
  u64 e2 = ADD2(v[2], v[5]), e3 = ADD2(v[3], v[4]);
  u64 o0 = SUB2(v[0], v[7]), o1 = SUB2(v[1], v[6]);
  u64 o2 = SUB2(v[2], v[5]), o3 = SUB2(v[3], v[4]);
  u64 s03 = ADD2(e0, e3), s12 = ADD2(e1, e2);
  u64 d03 = SUB2(e0, e3), d12 = SUB2(e1, e2);
  v[0] = ADD2(s03, s12);
  v[4] = MUL2(C[K_C4], SUB2(s03, s12));
  v[2] = FMA2(C[K_C6], d12, MUL2(C[K_C2], d03));
  v[6] = SUB2(MUL2(C[K_C6], d03), MUL2(C[K_C2], d12));
  v[1] = FMA2(C[K_C7], o3, FMA2(C[K_C5], o2, FMA2(C[K_C3], o1, MUL2(C[K_C1], o0))));
  v[3] = SUB2(MUL2(C[K_C3], o0),
              FMA2(C[K_C7], o1, FMA2(C[K_C1], o2, MUL2(C[K_C5], o3))));
  v[5] = SUB2(FMA2(C[K_C7], o2, FMA2(C[K_C3], o3, MUL2(C[K_C5], o0))),
              MUL2(C[K_C1], o1));
  v[7] = SUB2(FMA2(C[K_C3], o2, MUL2(C[K_C7], o0)),
              FMA2(C[K_C1], o3, MUL2(C[K_C5], o1)));
}

// Packed 8-point IDCT (alpha folded into tables)
__device__ __forceinline__ void idct2(u64* v, const u64* C) {
  u64 t = MUL2(C[K_C4], v[4]);
  u64 p = ADD2(v[0], t);
  u64 m = SUB2(v[0], t);
  u64 u1 = FMA2(C[K_C6], v[6], MUL2(C[K_C2], v[2]));
  u64 u2 = SUB2(MUL2(C[K_C6], v[2]), MUL2(C[K_C2], v[6]));
  u64 ev0 = ADD2(p, u1), ev3 = SUB2(p, u1);
  u64 ev1 = ADD2(m, u2), ev2 = SUB2(m, u2);
  u64 i1 = v[1], i3 = v[3], i5 = v[5], i7 = v[7];
  u64 od0 = FMA2(C[K_C7], i7, FMA2(C[K_C5], i5, FMA2(C[K_C3], i3, MUL2(C[K_C1], i1))));
  u64 od1 = SUB2(MUL2(C[K_C3], i1),
                 FMA2(C[K_C7], i3, FMA2(C[K_C1], i5, MUL2(C[K_C5], i7))));
  u64 od2 = SUB2(FMA2(C[K_C7], i5, FMA2(C[K_C3], i7, MUL2(C[K_C5], i1))),
                 MUL2(C[K_C1], i3));
  u64 od3 = SUB2(FMA2(C[K_C3], i5, MUL2(C[K_C7], i1)),
                 FMA2(C[K_C1], i7, MUL2(C[K_C5], i3)));
  v[0] = ADD2(ev0, od0);  v[7] = SUB2(ev0, od0);
  v[1] = ADD2(ev1, od1);  v[6] = SUB2(ev1, od1);
  v[2] = ADD2(ev2, od2);  v[5] = SUB2(ev2, od2);
  v[3] = ADD2(ev3, od3);  v[4] = SUB2(ev3, od3);
}

// Lane-pair half row-DCT (even lane: natural px, odd lane: reversed px)
__device__ __forceinline__ void half_dct(float v[4], const float cf[16], float sgn) {
  float t0 = __shfl_xor_sync(0xffffffffu, v[0], 1);
  float t1 = __shfl_xor_sync(0xffffffffu, v[1], 1);
  float t2 = __shfl_xor_sync(0xffffffffu, v[2], 1);
  float t3 = __shfl_xor_sync(0xffffffffu, v[3], 1);
  float x0 = fmaf(sgn, v[0], t0);
  float x1 = fmaf(sgn, v[1], t1);
  float x2 = fmaf(sgn, v[2], t2);
  float x3 = fmaf(sgn, v[3], t3);
  v[0] = fmaf(cf[3],  x3, fmaf(cf[2],  x2, fmaf(cf[1],  x1, cf[0]  * x0)));
  v[1] = fmaf(cf[7],  x3, fmaf(cf[6],  x2, fmaf(cf[5],  x1, cf[4]  * x0)));
  v[2] = fmaf(cf[11], x3, fmaf(cf[10], x2, fmaf(cf[9],  x1, cf[8]  * x0)));
  v[3] = fmaf(cf[15], x3, fmaf(cf[14], x2, fmaf(cf[13], x1, cf[12] * x0)));
}

// Lane-pair half row-IDCT (even lane out: natural px, odd lane out: reversed px)
__device__ __forceinline__ void half_idct(float f[4], const float ci[16], float sgn) {
  float g0 = fmaf(ci[3],  f[3], fmaf(ci[2],  f[2], fmaf(ci[1],  f[1], ci[0]  * f[0])));
  float g1 = fmaf(ci[7],  f[3], fmaf(ci[6],  f[2], fmaf(ci[5],  f[1], ci[4]  * f[0])));
  float g2 = fmaf(ci[11], f[3], fmaf(ci[10], f[2], fmaf(ci[9],  f[1], ci[8]  * f[0])));
  float g3 = fmaf(ci[15], f[3], fmaf(ci[14], f[2], fmaf(ci[13], f[1], ci[12] * f[0])));
  float t0 = __shfl_xor_sync(0xffffffffu, g0, 1);
  float t1 = __shfl_xor_sync(0xffffffffu, g1, 1);
  float t2 = __shfl_xor_sync(0xffffffffu, g2, 1);
  float t3 = __shfl_xor_sync(0xffffffffu, g3, 1);
  f[0] = fmaf(sgn, g0, t0);
  f[1] = fmaf(sgn, g1, t1);
  f[2] = fmaf(sgn, g2, t2);
  f[3] = fmaf(sgn, g3, t3);
}

__global__ void __launch_bounds__(256, 5)
jpeg_kernel(const float* __restrict__ in, float* __restrict__ out) {
  extern __shared__ float sm[];   // 3*2048 plane floats + 128 ulonglong2 table
  ulonglong2* sQ2 = (ulonglong2*)(sm + 3 * PL);   // fused table {qa2, qb2}

  const int tid = threadIdx.x;
  const bool oddl = (tid & 1) != 0;
  const float sgn = oddl ? -1.f : 1.f;
  const int gx0 = blockIdx.x * TW;
  const int gy0 = blockIdx.y * TH;
  const size_t plane = (size_t)Hh * Ww;
  const size_t img = (size_t)blockIdx.z * 3 * plane;
  const float* __restrict__ pr = in + img;
  const float* __restrict__ pg = in + img + plane;
  const float* __restrict__ pb = in + img + 2 * plane;

  // ---- fused quant table fill (slot s holds freq perm[s]={0,2,4,6,1,3,5,7};
  //      entry (tab,u,s) packs {qa(s),qa(s+1)} and {qb(s),qb(s+1)}) ----
  if (tid < 128) {
    int tab = tid >> 6, uv = tid & 63, u = uv >> 3, s = uv & 7;
    int s1 = (s < 7) ? s + 1 : 7;
    int v0 = (s < 4) ? (s << 1) : ((s << 1) - 7);
    int v1 = (s1 < 4) ? (s1 << 1) : ((s1 << 1) - 7);
    float au = u ? 1.f : 0.70710678118654752f;
    float a0 = 0.25f * au * (v0 ? 1.f : 0.70710678118654752f);
    float a1 = 0.25f * au * (v1 ? 1.f : 0.70710678118654752f);
    float Q0 = tab ? QC[u * 8 + v0] : QY[u * 8 + v0];
    float Q1 = tab ? QC[u * 8 + v1] : QY[u * 8 + v1];
    ulonglong2 e;
    e.x = F2PK(a0 / Q0, a1 / Q1);
    e.y = F2PK(a0 * Q0, a1 * Q1);
    sQ2[tid] = e;
  }

  // ------- Phase 1: gmem -> YCbCr -> half row-DCT -> smem (channel-serial) -------
  {
    float cf[16];
    const float* cfp = CF + (oddl ? 16 : 0);
#pragma unroll
    for (int t = 0; t < 16; ++t) cf[t] = cfp[t];

#pragma unroll
    for (int it = 0; it < 2; ++it) {
      int i = tid + it * 256;
      int row = i >> 4;                 // 0..31
      int c4 = (i & 15) << 2;
      size_t g = (size_t)(gy0 + row) * Ww + (gx0 + c4);
      float4 r4 = *(const float4*)(pr + g);
      float4 g4 = *(const float4*)(pg + g);
      float4 b4 = *(const float4*)(pb + g);

      // odd lanes reverse their 4 pixels (pixel order 8j+7..8j+4)
      float R[4], G[4], B[4];
      R[0] = oddl ? r4.w : r4.x;  R[1] = oddl ? r4.z : r4.y;
      R[2] = oddl ? r4.y : r4.z;  R[3] = oddl ? r4.x : r4.w;
      G[0] = oddl ? g4.w : g4.x;  G[1] = oddl ? g4.z : g4.y;
      G[2] = oddl ? g4.y : g4.z;  G[3] = oddl ? g4.x : g4.w;
      B[0] = oddl ? b4.w : b4.x;  B[1] = oddl ? b4.z : b4.y;
      B[2] = oddl ? b4.y : b4.z;  B[3] = oddl ? b4.x : b4.w;

      int s = row * 64 + swzc(c4);

      float ch[4];
#pragma unroll
      for (int q = 0; q < 4; ++q)   // Y ((x+1)/2*255 folded in)
        ch[q] = fmaf(38.1225f, R[q], fmaf(74.8425f, G[q], fmaf(14.535f, B[q], 127.5f)));
      half_dct(ch, cf, sgn);
      *(float4*)&sm[s] = make_float4(ch[0], ch[1], ch[2], ch[3]);

#pragma unroll
      for (int q = 0; q < 4; ++q)   // Cb
        ch[q] = fmaf(-21.51384f, R[q], fmaf(-42.23616f, G[q], fmaf(63.75f, B[q], 128.f)));
      half_dct(ch, cf, sgn);
      *(float4*)&sm[PL + s] = make_float4(ch[0], ch[1], ch[2], ch[3]);

#pragma unroll
      for (int q = 0; q < 4; ++q)   // Cr
        ch[q] = fmaf(63.75f, R[q], fmaf(-53.38272f, G[q], fmaf(-10.36728f, B[q], 128.f)));
      half_dct(ch, cf, sgn);
      *(float4*)&sm[2 * PL + s] = make_float4(ch[0], ch[1], ch[2], ch[3]);
    }
  }
  __syncthreads();

  // --- Phase 2: packed f32x2 column pass, ALL 256 threads.
  // 384 packed column-vector items: item0 = channels 0,1 (all 256 threads),
  // item1 = channel 2 (threads 0..127). Conflict-free u64 accesses:
  // each 16-lane group spans all 32 banks exactly once.
  {
    u64 C[K_NUM];
    C[K_C4] = F2PK(0.70710678f, 0.70710678f);
    C[K_C2] = F2PK(0.92387953f, 0.92387953f);
    C[K_C6] = F2PK(0.38268343f, 0.38268343f);
    C[K_C1] = F2PK(0.98078528f, 0.98078528f);
    C[K_C3] = F2PK(0.83146961f, 0.83146961f);
    C[K_C5] = F2PK(0.55557023f, 0.55557023f);
    C[K_C7] = F2PK(0.19509032f, 0.19509032f);
    const u64 MAG = F2PK(12582912.f, 12582912.f);   // 1.5*2^23 (RNE magic)

#pragma unroll
    for (int item = 0; item < 2; ++item) {
      int chn, rem;
      if (item == 0) { chn = tid >> 7; rem = tid & 127; }
      else {
        if (tid >= 128) break;
        chn = 2; rem = tid;
      }
      const int c2 = (rem & 31) << 1;       // even column 0..62
      const int br = rem >> 5;              // block-row 0..3
      const int slot = c2 & 7;              // 0,2,4,6
      const int qbase = (chn ? 64 : 0) + slot;
      const int adr = chn * PL + br * 512 + swzc(c2);

      u64 v[8];
#pragma unroll
      for (int r = 0; r < 8; ++r)
        v[r] = *(const u64*)&sm[adr + r * 64];
      dct2(v, C);
      if (slot == 0)                        // DC column (lo element)
        v[0] = ADD2(v[0], F2PK(-8192.f, 0.f));
#pragma unroll
      for (int u = 0; u < 8; ++u) {
        ulonglong2 q = sQ2[qbase + u * 8];  // one LDS.128: {qa2, qb2}
        u64 s = MUL2(v[u], q.x);
        u64 r = SUB2(ADD2(s, MAG), MAG);    // RNE round
        u64 d = SUB2(s, r);
        v[u] = MUL2(FMA2(MUL2(d, d), d, r), q.y);   // diff_round + dequant
      }
      idct2(v, C);
#pragma unroll
      for (int r = 0; r < 8; ++r)
        *(u64*)&sm[adr + r * 64] = v[r];
    }
  }
  __syncthreads();

  // ------- Phase 3: smem -> half row-IDCT (x 1/255) -> RGB -> gmem -------
  {
    float ci[16];
    const float* cip = CI + (oddl ? 16 : 0);
    const float inv255 = 1.0f / 255.0f;
#pragma unroll
    for (int t = 0; t < 16; ++t) ci[t] = cip[t] * inv255;   // fold 1/255

    float* __restrict__ qr = out + img;
    float* __restrict__ qg = out + img + plane;
    float* __restrict__ qb2 = out + img + 2 * plane;

#pragma unroll
    for (int it = 0; it < 2; ++it) {
      int i = tid + it * 256;
      int row = i >> 4;
      int c4 = (i & 15) << 2;
      int s = row * 64 + swzc(c4);

      float y[4], cb[4], cr[4];
      float4 t4;
      t4 = *(const float4*)&sm[s];
      y[0]=t4.x; y[1]=t4.y; y[2]=t4.z; y[3]=t4.w;
      half_idct(y, ci, sgn);
      t4 = *(const float4*)&sm[PL + s];
      cb[0]=t4.x; cb[1]=t4.y; cb[2]=t4.z; cb[3]=t4.w;
      half_idct(cb, ci, sgn);
      t4 = *(const float4*)&sm[2 * PL + s];
      cr[0]=t4.x; cr[1]=t4.y; cr[2]=t4.z; cr[3]=t4.w;
      half_idct(cr, ci, sgn);

      float R[4], G[4], B[4];
#pragma unroll
      for (int q = 0; q < 4; ++q) {
        float y128 = y[q] + 0.501960784f;    // += 128/255 (DC trick, scaled)
        R[q] = __saturatef(fmaf(1.402f, cr[q], y128));
        G[q] = __saturatef(fmaf(-0.714136f, cr[q], fmaf(-0.344136f, cb[q], y128)));
        B[q] = __saturatef(fmaf(1.772f, cb[q], y128));
      }
      size_t g = (size_t)(gy0 + row) * Ww + (gx0 + c4);
      float4 ro = oddl ? make_float4(R[3], R[2], R[1], R[0]) : make_float4(R[0], R[1], R[2], R[3]);
      float4 go = oddl ? make_float4(G[3], G[2], G[1], G[0]) : make_float4(G[0], G[1], G[2], G[3]);
      float4 bo = oddl ? make_float4(B[3], B[2], B[1], B[0]) : make_float4(B[0], B[1], B[2], B[3]);
      *(float4*)(qr + g)  = ro;
      *(float4*)(qg + g)  = go;
      *(float4*)(qb2 + g) = bo;
    }
  }
}

} // namespace

extern "C" void kernel_launch(void* const* d_in, const int* in_sizes, int n_in,
                              void* d_out, int out_size) {
  (void)in_sizes; (void)n_in; (void)out_size;
  const float* in = (const float*)d_in[0];
  float* out = (float*)d_out;
  constexpr int SMEM = 3 * PL * 4 + 128 * 16;   // 24576 + 2048 = 26624 bytes
  static bool attr_set = false;
  if (!attr_set) {
    cudaFuncSetAttribute(jpeg_kernel, cudaFuncAttributeMaxDynamicSharedMemorySize, SMEM);
    attr_set = true;
  }
  dim3 grid(Ww / TW, Hh / TH, 16);
  jpeg_kernel<<<grid, 256, SMEM>>>(in, out);
}

// round 14
// speedup vs baseline: 1.0932x; 1.0013x over previous
#include <cuda_runtime.h>

// JPEG compress/decompress (DiffJPEG, factor=1.0) for [16,3,512,512] fp32 in [-1,1].
// One CTA = one 64x32 tile, 256 threads, 5 CTAs/SM.
// Phase 1: gmem -> YCbCr -> lane-pair half row-DCT -> smem (permuted freq slots)
// Phase 2: packed f32x2 column pass, ALL 256 threads (384 work items).
// Phase 3: smem -> half row-IDCT (coeffs pre-scaled by 1/255) -> RGB -> gmem.
// Lane-parity reversal is absorbed into the constant tables: shuffles are
// consumed in reversed index order (t[3-k]) so odd lanes keep natural pixel
// order end-to-end (no SELs). DC trick: subtract 128*64 from the DC coeff.

namespace {

constexpr int Hh = 512;
constexpr int Ww = 512;
constexpr int TW = 64;
constexpr int TH = 32;
constexpr int PL = TW * TH;   // 2048 floats per channel plane

typedef unsigned long long u64;

__device__ __forceinline__ u64 F2PK(float a, float b) {
  u64 r; asm("mov.b64 %0,{%1,%2};" : "=l"(r) : "f"(a), "f"(b)); return r;
}
__device__ __forceinline__ u64 FMA2(u64 a, u64 b, u64 c) {
  u64 d; asm("fma.rn.f32x2 %0,%1,%2,%3;" : "=l"(d) : "l"(a), "l"(b), "l"(c)); return d;
}
__device__ __forceinline__ u64 ADD2(u64 a, u64 b) {
  u64 d; asm("add.rn.f32x2 %0,%1,%2;" : "=l"(d) : "l"(a), "l"(b)); return d;
}
__device__ __forceinline__ u64 SUB2(u64 a, u64 b) {
  u64 d; asm("sub.rn.f32x2 %0,%1,%2;" : "=l"(d) : "l"(a), "l"(b)); return d;
}
__device__ __forceinline__ u64 MUL2(u64 a, u64 b) {
  u64 d; asm("mul.rn.f32x2 %0,%1,%2;" : "=l"(d) : "l"(a), "l"(b)); return d;
}

// Forward half-transform coefs.
// Even lanes (p=0): CF[m][k] = Dm[2m][k]   (unchanged).
// Odd lanes (p=1):  CF'[m][k] = Dm[2m+1][3-k]  (column-reversed: odd lane's
// butterfly output x_k = o_{3-k} when using t[3-k]).
__constant__ float CF[32] = {
  1.f,          1.f,          1.f,          1.f,
  0.92387953f,  0.38268343f, -0.38268343f, -0.92387953f,
  0.70710678f, -0.70710678f, -0.70710678f,  0.70710678f,
  0.38268343f, -0.92387953f,  0.92387953f, -0.38268343f,
  0.19509032f,  0.55557023f,  0.83146961f,  0.98078528f,
 -0.55557023f, -0.98078528f, -0.19509032f,  0.83146961f,
  0.83146961f,  0.19509032f, -0.98078528f,  0.55557023f,
 -0.98078528f,  0.83146961f, -0.55557023f,  0.19509032f,
};
// Inverse half-transform coefs.
// Even lanes: CI[k][m] = Dm[2m][k] (unchanged).
// Odd lanes: CI'[k][m] = Dm[2m+1][3-k] (row-reversed: odd lane's g_k = od_{3-k},
// so f_k = -g_k + t[3-k] = ev_{3-k} - od_{3-k} = px_{4+k}, natural order).
__constant__ float CI[32] = {
  1.f,  0.92387953f,  0.70710678f,  0.38268343f,
  1.f,  0.38268343f, -0.70710678f, -0.92387953f,
  1.f, -0.38268343f, -0.70710678f,  0.92387953f,
  1.f, -0.92387953f,  0.70710678f, -0.38268343f,
  0.19509032f, -0.55557023f,  0.83146961f, -0.98078528f,
  0.55557023f, -0.98078528f,  0.19509032f,  0.83146961f,
  0.83146961f, -0.19509032f, -0.98078528f, -0.55557023f,
  0.98078528f,  0.83146961f,  0.55557023f,  0.19509032f,
};

__device__ static const float QY[64] = {
  16, 11, 10, 16, 24, 40, 51, 61,
  12, 12, 14, 19, 26, 58, 60, 55,
  14, 13, 16, 24, 40, 57, 69, 56,
  14, 17, 22, 29, 51, 87, 80, 62,
  18, 22, 37, 56, 68, 109, 103, 77,
  24, 35, 55, 64, 81, 104, 113, 92,
  49, 64, 78, 87, 103, 121, 120, 101,
  72, 92, 95, 98, 112, 100, 103, 99
};
__device__ static const float QC[64] = {
  17, 18, 24, 47, 99, 99, 99, 99,
  18, 21, 26, 66, 99, 99, 99, 99,
  24, 26, 56, 99, 99, 99, 99, 99,
  47, 66, 99, 99, 99, 99, 99, 99,
  99, 99, 99, 99, 99, 99, 99, 99,
  99, 99, 99, 99, 99, 99, 99, 99,
  99, 99, 99, 99, 99, 99, 99, 99,
  99, 99, 99, 99, 99, 99, 99, 99
};

__device__ __forceinline__ int swzc(int c) { return c ^ ((c & 32) >> 3); }

// Packed coefficient indices (positive only; signs via SUB2)
enum { K_C4 = 0, K_C2, K_C6, K_C1, K_C3, K_C5, K_C7, K_NUM };

// Packed 8-point DCT-II (two independent columns per u64)
__device__ __forceinline__ void dct2(u64* v, const u64* C) {
  u64 e0 = ADD2(v[0], v[7]), e1 = ADD2(v[1], v[6]);
  u64 e2 = ADD2(v[2], v[5]), e3 = ADD2(v[3], v[4]);
  u64 o0 = SUB2(v[0], v[7]), o1 = SUB2(v[1], v[6]);
  u64 o2 = SUB2(v[2], v[5]), o3 = SUB2(v[3], v[4]);
  u64 s03 = ADD2(e0, e3), s12 = ADD2(e1, e2);
  u64 d03 = SUB2(e0, e3), d12 = SUB2(e1, e2);
  v[0] = ADD2(s03, s12);
  v[4] = MUL2(C[K_C4], SUB2(s03, s12));
  v[2] = FMA2(C[K_C6], d12, MUL2(C[K_C2], d03));
  v[6] = SUB2(MUL2(C[K_C6], d03), MUL2(C[K_C2], d12));
  v[1] = FMA2(C[K_C7], o3, FMA2(C[K_C5], o2, FMA2(C[K_C3], o1, MUL2(C[K_C1], o0))));
  v[3] = SUB2(MUL2(C[K_C3], o0),
              FMA2(C[K_C7], o1, FMA2(C[K_C1], o2, MUL2(C[K_C5], o3))));
  v[5] = SUB2(FMA2(C[K_C7], o2, FMA2(C[K_C3], o3, MUL2(C[K_C5], o0))),
              MUL2(C[K_C1], o1));
  v[7] = SUB2(FMA2(C[K_C3], o2, MUL2(C[K_C7], o0)),
              FMA2(C[K_C1], o3, MUL2(C[K_C5], o1)));
}

// Packed 8-point IDCT (alpha folded into tables)
__device__ __forceinline__ void idct2(u64* v, const u64* C) {
  u64 t = MUL2(C[K_C4], v[4]);
  u64 p = ADD2(v[0], t);
  u64 m = SUB2(v[0], t);
  u64 u1 = FMA2(C[K_C6], v[6], MUL2(C[K_C2], v[2]));
  u64 u2 = SUB2(MUL2(C[K_C6], v[2]), MUL2(C[K_C2], v[6]));
  u64 ev0 = ADD2(p, u1), ev3 = SUB2(p, u1);
  u64 ev1 = ADD2(m, u2), ev2 = SUB2(m, u2);
  u64 i1 = v[1], i3 = v[3], i5 = v[5], i7 = v[7];
  u64 od0 = FMA2(C[K_C7], i7, FMA2(C[K_C5], i5, FMA2(C[K_C3], i3, MUL2(C[K_C1], i1))));
  u64 od1 = SUB2(MUL2(C[K_C3], i1),
                 FMA2(C[K_C7], i3, FMA2(C[K_C1], i5, MUL2(C[K_C5], i7))));
  u64 od2 = SUB2(FMA2(C[K_C7], i5, FMA2(C[K_C3], i7, MUL2(C[K_C5], i1))),
                 MUL2(C[K_C1], i3));
  u64 od3 = SUB2(FMA2(C[K_C3], i5, MUL2(C[K_C7], i1)),
                 FMA2(C[K_C1], i7, MUL2(C[K_C5], i3)));
  v[0] = ADD2(ev0, od0);  v[7] = SUB2(ev0, od0);
  v[1] = ADD2(ev1, od1);  v[6] = SUB2(ev1, od1);
  v[2] = ADD2(ev2, od2);  v[5] = SUB2(ev2, od2);
  v[3] = ADD2(ev3, od3);  v[4] = SUB2(ev3, od3);
}

// Lane-pair half row-DCT, natural pixel order both lanes.
// x_k = sgn*v_k + t_{3-k}: even lane -> e_k, odd lane -> o_{3-k} (CF' absorbs).
__device__ __forceinline__ void half_dct(float v[4], const float cf[16], float sgn) {
  float t0 = __shfl_xor_sync(0xffffffffu, v[0], 1);
  float t1 = __shfl_xor_sync(0xffffffffu, v[1], 1);
  float t2 = __shfl_xor_sync(0xffffffffu, v[2], 1);
  float t3 = __shfl_xor_sync(0xffffffffu, v[3], 1);
  float x0 = fmaf(sgn, v[0], t3);
  float x1 = fmaf(sgn, v[1], t2);
  float x2 = fmaf(sgn, v[2], t1);
  float x3 = fmaf(sgn, v[3], t0);
  v[0] = fmaf(cf[3],  x3, fmaf(cf[2],  x2, fmaf(cf[1],  x1, cf[0]  * x0)));
  v[1] = fmaf(cf[7],  x3, fmaf(cf[6],  x2, fmaf(cf[5],  x1, cf[4]  * x0)));
  v[2] = fmaf(cf[11], x3, fmaf(cf[10], x2, fmaf(cf[9],  x1, cf[8]  * x0)));
  v[3] = fmaf(cf[15], x3, fmaf(cf[14], x2, fmaf(cf[13], x1, cf[12] * x0)));
}

// Lane-pair half row-IDCT, natural pixel order out on both lanes.
// f_k = sgn*g_k + t_{3-k}: even -> px_k, odd -> px_{4+k} (CI' absorbs).
__device__ __forceinline__ void half_idct(float f[4], const float ci[16], float sgn) {
  float g0 = fmaf(ci[3],  f[3], fmaf(ci[2],  f[2], fmaf(ci[1],  f[1], ci[0]  * f[0])));
  float g1 = fmaf(ci[7],  f[3], fmaf(ci[6],  f[2], fmaf(ci[5],  f[1], ci[4]  * f[0])));
  float g2 = fmaf(ci[11], f[3], fmaf(ci[10], f[2], fmaf(ci[9],  f[1], ci[8]  * f[0])));
  float g3 = fmaf(ci[15], f[3], fmaf(ci[14], f[2], fmaf(ci[13], f[1], ci[12] * f[0])));
  float t0 = __shfl_xor_sync(0xffffffffu, g0, 1);
  float t1 = __shfl_xor_sync(0xffffffffu, g1, 1);
  float t2 = __shfl_xor_sync(0xffffffffu, g2, 1);
  float t3 = __shfl_xor_sync(0xffffffffu, g3, 1);
  f[0] = fmaf(sgn, g0, t3);
  f[1] = fmaf(sgn, g1, t2);
  f[2] = fmaf(sgn, g2, t1);
  f[3] = fmaf(sgn, g3, t0);
}

__global__ void __launch_bounds__(256, 5)
jpeg_kernel(const float* __restrict__ in, float* __restrict__ out) {
  extern __shared__ float sm[];   // 3*2048 plane floats + 128 ulonglong2 table
  ulonglong2* sQ2 = (ulonglong2*)(sm + 3 * PL);   // fused table {qa2, qb2}

  const int tid = threadIdx.x;
  const bool oddl = (tid & 1) != 0;
  const float sgn = oddl ? -1.f : 1.f;
  const int gx0 = blockIdx.x * TW;
  const int gy0 = blockIdx.y * TH;
  const size_t plane = (size_t)Hh * Ww;
  const size_t img = (size_t)blockIdx.z * 3 * plane;
  const float* __restrict__ pr = in + img;
  const float* __restrict__ pg = in + img + plane;
  const float* __restrict__ pb = in + img + 2 * plane;

  // ---- fused quant table fill (slot s holds freq perm[s]={0,2,4,6,1,3,5,7};
  //      entry (tab,u,s) packs {qa(s),qa(s+1)} and {qb(s),qb(s+1)}) ----
  if (tid < 128) {
    int tab = tid >> 6, uv = tid & 63, u = uv >> 3, s = uv & 7;
    int s1 = (s < 7) ? s + 1 : 7;
    int v0 = (s < 4) ? (s << 1) : ((s << 1) - 7);
    int v1 = (s1 < 4) ? (s1 << 1) : ((s1 << 1) - 7);
    float au = u ? 1.f : 0.70710678118654752f;
    float a0 = 0.25f * au * (v0 ? 1.f : 0.70710678118654752f);
    float a1 = 0.25f * au * (v1 ? 1.f : 0.70710678118654752f);
    float Q0 = tab ? QC[u * 8 + v0] : QY[u * 8 + v0];
    float Q1 = tab ? QC[u * 8 + v1] : QY[u * 8 + v1];
    ulonglong2 e;
    e.x = F2PK(a0 / Q0, a1 / Q1);
    e.y = F2PK(a0 * Q0, a1 * Q1);
    sQ2[tid] = e;
  }

  // ------- Phase 1: gmem -> YCbCr -> half row-DCT -> smem (channel-serial) -------
  {
    float cf[16];
    const float* cfp = CF + (oddl ? 16 : 0);
#pragma unroll
    for (int t = 0; t < 16; ++t) cf[t] = cfp[t];

#pragma unroll
    for (int it = 0; it < 2; ++it) {
      int i = tid + it * 256;
      int row = i >> 4;                 // 0..31
      int c4 = (i & 15) << 2;
      size_t g = (size_t)(gy0 + row) * Ww + (gx0 + c4);
      float4 r4 = *(const float4*)(pr + g);
      float4 g4 = *(const float4*)(pg + g);
      float4 b4 = *(const float4*)(pb + g);

      float R[4] = { r4.x, r4.y, r4.z, r4.w };
      float G[4] = { g4.x, g4.y, g4.z, g4.w };
      float B[4] = { b4.x, b4.y, b4.z, b4.w };

      int s = row * 64 + swzc(c4);

      float ch[4];
#pragma unroll
      for (int q = 0; q < 4; ++q)   // Y ((x+1)/2*255 folded in)
        ch[q] = fmaf(38.1225f, R[q], fmaf(74.8425f, G[q], fmaf(14.535f, B[q], 127.5f)));
      half_dct(ch, cf, sgn);
      *(float4*)&sm[s] = make_float4(ch[0], ch[1], ch[2], ch[3]);

#pragma unroll
      for (int q = 0; q < 4; ++q)   // Cb
        ch[q] = fmaf(-21.51384f, R[q], fmaf(-42.23616f, G[q], fmaf(63.75f, B[q], 128.f)));
      half_dct(ch, cf, sgn);
      *(float4*)&sm[PL + s] = make_float4(ch[0], ch[1], ch[2], ch[3]);

#pragma unroll
      for (int q = 0; q < 4; ++q)   // Cr
        ch[q] = fmaf(63.75f, R[q], fmaf(-53.38272f, G[q], fmaf(-10.36728f, B[q], 128.f)));
      half_dct(ch, cf, sgn);
      *(float4*)&sm[2 * PL + s] = make_float4(ch[0], ch[1], ch[2], ch[3]);
    }
  }
  __syncthreads();

  // --- Phase 2: packed f32x2 column pass, ALL 256 threads.
  // 384 packed column-vector items: item0 = channels 0,1 (all 256 threads),
  // item1 = channel 2 (threads 0..127). Conflict-free u64 accesses.
  {
    u64 C[K_NUM];
    C[K_C4] = F2PK(0.70710678f, 0.70710678f);
    C[K_C2] = F2PK(0.92387953f, 0.92387953f);
    C[K_C6] = F2PK(0.38268343f, 0.38268343f);
    C[K_C1] = F2PK(0.98078528f, 0.98078528f);
    C[K_C3] = F2PK(0.83146961f, 0.83146961f);
    C[K_C5] = F2PK(0.55557023f, 0.55557023f);
    C[K_C7] = F2PK(0.19509032f, 0.19509032f);
    const u64 MAG = F2PK(12582912.f, 12582912.f);   // 1.5*2^23 (RNE magic)

#pragma unroll
    for (int item = 0; item < 2; ++item) {
      int chn, rem;
      if (item == 0) { chn = tid >> 7; rem = tid & 127; }
      else {
        if (tid >= 128) break;
        chn = 2; rem = tid;
      }
      const int c2 = (rem & 31) << 1;       // even column 0..62
      const int br = rem >> 5;              // block-row 0..3
      const int slot = c2 & 7;              // 0,2,4,6
      const int qbase = (chn ? 64 : 0) + slot;
      const int adr = chn * PL + br * 512 + swzc(c2);

      u64 v[8];
#pragma unroll
      for (int r = 0; r < 8; ++r)
        v[r] = *(const u64*)&sm[adr + r * 64];
      dct2(v, C);
      if (slot == 0)                        // DC column (lo element)
        v[0] = ADD2(v[0], F2PK(-8192.f, 0.f));
#pragma unroll
      for (int u = 0; u < 8; ++u) {
        ulonglong2 q = sQ2[qbase + u * 8];  // one LDS.128: {qa2, qb2}
        u64 s = MUL2(v[u], q.x);
        u64 r = SUB2(ADD2(s, MAG), MAG);    // RNE round
        u64 d = SUB2(s, r);
        v[u] = MUL2(FMA2(MUL2(d, d), d, r), q.y);   // diff_round + dequant
      }
      idct2(v, C);
#pragma unroll
      for (int r = 0; r < 8; ++r)
        *(u64*)&sm[adr + r * 64] = v[r];
    }
  }
  __syncthreads();

  // ------- Phase 3: smem -> half row-IDCT (x 1/255) -> RGB -> gmem -------
  {
    float ci[16];
    const float* cip = CI + (oddl ? 16 : 0);
    const float inv255 = 1.0f / 255.0f;
#pragma unroll
    for (int t = 0; t < 16; ++t) ci[t] = cip[t] * inv255;   // fold 1/255

    float* __restrict__ qr = out + img;
    float* __restrict__ qg = out + img + plane;
    float* __restrict__ qb2 = out + img + 2 * plane;

#pragma unroll
    for (int it = 0; it < 2; ++it) {
      int i = tid + it * 256;
      int row = i >> 4;
      int c4 = (i & 15) << 2;
      int s = row * 64 + swzc(c4);

      float y[4], cb[4], cr[4];
      float4 t4;
      t4 = *(const float4*)&sm[s];
      y[0]=t4.x; y[1]=t4.y; y[2]=t4.z; y[3]=t4.w;
      half_idct(y, ci, sgn);
      t4 = *(const float4*)&sm[PL + s];
      cb[0]=t4.x; cb[1]=t4.y; cb[2]=t4.z; cb[3]=t4.w;
      half_idct(cb, ci, sgn);
      t4 = *(const float4*)&sm[2 * PL + s];
      cr[0]=t4.x; cr[1]=t4.y; cr[2]=t4.z; cr[3]=t4.w;
      half_idct(cr, ci, sgn);

      float R[4], G[4], B[4];
#pragma unroll
      for (int q = 0; q < 4; ++q) {
        float y128 = y[q] + 0.501960784f;    // += 128/255 (DC trick, scaled)
        R[q] = __saturatef(fmaf(1.402f, cr[q], y128));
        G[q] = __saturatef(fmaf(-0.714136f, cr[q], fmaf(-0.344136f, cb[q], y128)));
        B[q] = __saturatef(fmaf(1.772f, cb[q], y128));
      }
      size_t g = (size_t)(gy0 + row) * Ww + (gx0 + c4);
      *(float4*)(qr + g)  = make_float4(R[0], R[1], R[2], R[3]);
      *(float4*)(qg + g)  = make_float4(G[0], G[1], G[2], G[3]);
      *(float4*)(qb2 + g) = make_float4(B[0], B[1], B[2], B[3]);
    }
  }
}

} // namespace

extern "C" void kernel_launch(void* const* d_in, const int* in_sizes, int n_in,
                              void* d_out, int out_size) {
  (void)in_sizes; (void)n_in; (void)out_size;
  const float* in = (const float*)d_in[0];
  float* out = (float*)d_out;
  constexpr int SMEM = 3 * PL * 4 + 128 * 16;   // 24576 + 2048 = 26624 bytes
  static bool attr_set = false;
  if (!attr_set) {
    cudaFuncSetAttribute(jpeg_kernel, cudaFuncAttributeMaxDynamicSharedMemorySize, SMEM);
    attr_set = true;
  }
  dim3 grid(Ww / TW, Hh / TH, 16);
  jpeg_kernel<<<grid, 256, SMEM>>>(in, out);
}